// round 2
// baseline (speedup 1.0000x reference)
#include <cuda_runtime.h>
#include <cuda_bf16.h>

// out[b,s,n,c] = x[b,s,n,c] + pe[n,c],  x: (8,16,1024,256) fp32
// pe[n,2k]   = sin(n / (2000*k/256 + 0.01))
// pe[n,2k+1] = cos(n / (2000*k/256 + 0.01))   (same denom for the pair!)
//
// Single fused kernel: block (n, half) computes its pe row (128 sincosf)
// into SMEM, then streams 64 broadcast copies of row n with float4 +
// evict-first cache hints. No pe table in global memory, no second launch.

#define N_POS 1024
#define D_DIM 256
#define ROW_VEC (D_DIM / 4)     // 64 float4 per row
#define REPS 128                // B*S broadcast copies
#define REPS_PER_BLK 64         // gridDim.y = 2

__global__ void __launch_bounds__(256) add_pe_fused(const float4* __restrict__ x,
                                                    float4* __restrict__ out) {
    __shared__ float4 s_pe[ROW_VEC];

    const int n = blockIdx.x;           // position 0..1023
    const int t = threadIdx.x;

    // Build pe row for this n: threads 0..127 each handle one k (cols 2k, 2k+1)
    if (t < 128) {
        const float denom = (2000.0f / 256.0f) * (float)t + 0.01f;
        const float angle = (float)n / denom;
        float s, c;
        sincosf(angle, &s, &c);
        reinterpret_cast<float2*>(s_pe)[t] = make_float2(s, c);
    }
    __syncthreads();

    const int lane = t & (ROW_VEC - 1);   // float4 index within row, 0..63
    const int rsub = t >> 6;              // 0..3
    const float4 p = s_pe[lane];

    const int r0 = blockIdx.y * REPS_PER_BLK;
    // Each thread handles reps r0+rsub, r0+rsub+4, ... (16 iterations)
#pragma unroll 4
    for (int r = r0 + rsub; r < r0 + REPS_PER_BLK; r += 4) {
        const size_t idx = ((size_t)r * N_POS + n) * ROW_VEC + lane;
        float4 a = __ldcs(&x[idx]);
        a.x += p.x; a.y += p.y; a.z += p.z; a.w += p.w;
        __stcs(&out[idx], a);
    }
}

extern "C" void kernel_launch(void* const* d_in, const int* in_sizes, int n_in,
                              void* d_out, int out_size) {
    const float4* x = (const float4*)d_in[0];
    float4* out = (float4*)d_out;
    dim3 grid(N_POS, REPS / REPS_PER_BLK, 1);   // (1024, 2)
    add_pe_fused<<<grid, 256>>>(x, out);
}

// round 3
// speedup vs baseline: 1.0688x; 1.0688x over previous
#include <cuda_runtime.h>
#include <cuda_bf16.h>

// out[b,s,n,c] = x[b,s,n,c] + pe[n,c],  x: (8,16,1024,256) fp32
// pe[n,2k]   = sin(n / (2000*k/256 + 0.01))
// pe[n,2k+1] = cos(n / (2000*k/256 + 0.01))   (pair shares denom -> sincosf)
//
// Fused single kernel. Block (n, half): compute pe row into SMEM (128
// sincosf), then stream 64 broadcast reps. Key change vs R2: 4 independent
// batched loads per iteration (MLP=4 per thread) before any add/store.

#define N_POS 1024
#define D_DIM 256
#define ROW_VEC (D_DIM / 4)     // 64 float4 per row
#define REPS 128                // B*S
#define REPS_PER_BLK 64         // gridDim.y = 2
#define BATCH 4

__global__ void __launch_bounds__(256) add_pe_fused(const float4* __restrict__ x,
                                                    float4* __restrict__ out) {
    __shared__ float4 s_pe[ROW_VEC];

    const int n = blockIdx.x;           // position 0..1023
    const int t = threadIdx.x;

    if (t < 128) {
        const float denom = (2000.0f / 256.0f) * (float)t + 0.01f;
        float s, c;
        sincosf((float)n / denom, &s, &c);
        reinterpret_cast<float2*>(s_pe)[t] = make_float2(s, c);
    }
    __syncthreads();

    const int lane = t & (ROW_VEC - 1);   // 0..63 float4 within row
    const int rsub = t >> 6;              // 0..3
    const float4 p = s_pe[lane];

    // Thread handles reps: r0 + rsub + 4*j, j = 0..15, in 4 batches of 4.
    // Row stride in float4 units: N_POS * ROW_VEC = 65536 (1 MB / 16).
    const size_t rstride = (size_t)N_POS * ROW_VEC;          // per-rep stride
    const int r0 = blockIdx.y * REPS_PER_BLK + rsub;
    size_t base = ((size_t)r0 * N_POS + n) * ROW_VEC + lane;
    const size_t bstride = 4 * rstride;                       // between batched reps
    const size_t ostride = 16 * rstride;                      // between outer iters

#pragma unroll
    for (int it = 0; it < REPS_PER_BLK / (4 * BATCH); ++it) {
        const size_t b = base + (size_t)it * ostride;
        float4 a0 = __ldcs(&x[b + 0 * bstride]);
        float4 a1 = __ldcs(&x[b + 1 * bstride]);
        float4 a2 = __ldcs(&x[b + 2 * bstride]);
        float4 a3 = __ldcs(&x[b + 3 * bstride]);
        a0.x += p.x; a0.y += p.y; a0.z += p.z; a0.w += p.w;
        a1.x += p.x; a1.y += p.y; a1.z += p.z; a1.w += p.w;
        a2.x += p.x; a2.y += p.y; a2.z += p.z; a2.w += p.w;
        a3.x += p.x; a3.y += p.y; a3.z += p.z; a3.w += p.w;
        __stcs(&out[b + 0 * bstride], a0);
        __stcs(&out[b + 1 * bstride], a1);
        __stcs(&out[b + 2 * bstride], a2);
        __stcs(&out[b + 3 * bstride], a3);
    }
}

extern "C" void kernel_launch(void* const* d_in, const int* in_sizes, int n_in,
                              void* d_out, int out_size) {
    const float4* x = (const float4*)d_in[0];
    float4* out = (float4*)d_out;
    dim3 grid(N_POS, REPS / REPS_PER_BLK, 1);   // (1024, 2)
    add_pe_fused<<<grid, 256>>>(x, out);
}

// round 4
// speedup vs baseline: 1.0794x; 1.0099x over previous
#include <cuda_runtime.h>
#include <cuda_bf16.h>

// out[b,s,n,c] = x[b,s,n,c] + pe[n,c],  x: (8,16,1024,256) fp32
// pe[n,2k]   = sin(n / (2000*k/256 + 0.01))
// pe[n,2k+1] = cos(n / (2000*k/256 + 0.01))   (pair shares denom -> sincosf)
//
// Fused single kernel, block (n, half). R4: MLP=8 per thread — 8 independent
// batched loads, 8 adds, 8 burst stores. 32-bit indexing (8.4M float4 fits).

#define N_POS 1024
#define D_DIM 256
#define ROW_VEC (D_DIM / 4)     // 64 float4 per row
#define REPS 128                // B*S
#define REPS_PER_BLK 64         // gridDim.y = 2
#define BATCH 8

__global__ void __launch_bounds__(256) add_pe_fused(const float4* __restrict__ x,
                                                    float4* __restrict__ out) {
    __shared__ float4 s_pe[ROW_VEC];

    const int n = blockIdx.x;           // position 0..1023
    const int t = threadIdx.x;

    if (t < 128) {
        const float denom = (2000.0f / 256.0f) * (float)t + 0.01f;
        float s, c;
        sincosf((float)n / denom, &s, &c);
        reinterpret_cast<float2*>(s_pe)[t] = make_float2(s, c);
    }
    __syncthreads();

    const int lane = t & (ROW_VEC - 1);   // 0..63 float4 within row
    const int rsub = t >> 6;              // 0..3
    const float4 p = s_pe[lane];

    // Thread handles 16 reps: r0 + rsub + 4*j, j=0..15, as 2 batches of 8.
    const unsigned rstride = N_POS * ROW_VEC;             // 65536 float4 per rep
    const int r0 = blockIdx.y * REPS_PER_BLK + rsub;
    const unsigned base = (unsigned)(r0 * N_POS + n) * ROW_VEC + lane;
    const unsigned bstride = 4u * rstride;                // between batched reps
    const unsigned ostride = (unsigned)BATCH * bstride;   // between outer iters

#pragma unroll
    for (int it = 0; it < REPS_PER_BLK / (4 * BATCH); ++it) {   // 2 iters
        const unsigned b = base + (unsigned)it * ostride;
        float4 a[BATCH];
#pragma unroll
        for (int j = 0; j < BATCH; ++j)
            a[j] = __ldcs(&x[b + (unsigned)j * bstride]);
#pragma unroll
        for (int j = 0; j < BATCH; ++j) {
            a[j].x += p.x; a[j].y += p.y; a[j].z += p.z; a[j].w += p.w;
        }
#pragma unroll
        for (int j = 0; j < BATCH; ++j)
            __stcs(&out[b + (unsigned)j * bstride], a[j]);
    }
}

extern "C" void kernel_launch(void* const* d_in, const int* in_sizes, int n_in,
                              void* d_out, int out_size) {
    const float4* x = (const float4*)d_in[0];
    float4* out = (float4*)d_out;
    dim3 grid(N_POS, REPS / REPS_PER_BLK, 1);   // (1024, 2)
    add_pe_fused<<<grid, 256>>>(x, out);
}